// round 5
// baseline (speedup 1.0000x reference)
#include <cuda_runtime.h>
#include <cuda_bf16.h>
#include <stdint.h>

// GatherRouter combine: out[tag[i]] += data[i] over 65536 rows of 1024 fp32,
// into 16384 slots (tags int32, uniform). Two kernels:
//   k_bucket: fixed-capacity bucketing (counts ~Binom(65536,1/16384), max ~20,
//             CAP=64 gives astronomically safe headroom; overflow is dropped
//             rather than corrupting scratch).
//   k_reduce: one block per slot, dense coalesced float4 reduction, then
//             resets the slot's cursor so graph replays start from zero.
// __device__ globals are zero-initialized at load, so no init kernel needed.

#define NROWS   65536
#define DDIM    1024
#define NSLOTS  16384
#define CAP     64

__device__ int g_cursor[NSLOTS];           // zero at module load; reset by k_reduce
__device__ int g_rows[NSLOTS * CAP];       // 4 MB scratch

// ---------------------------------------------------------------------------
__global__ void k_bucket(const int* __restrict__ tags) {
    int i = blockIdx.x * blockDim.x + threadIdx.x;
    if (i < NROWS) {
        int t = tags[i] & (NSLOTS - 1);    // defensive mask (slots are pow2)
        int p = atomicAdd(&g_cursor[t], 1);
        if (p < CAP) g_rows[t * CAP + p] = i;
    }
}

// ---------------------------------------------------------------------------
// One block per output slot; 256 threads x float4 = 1024 floats per row.
__global__ __launch_bounds__(256) void k_reduce(const float* __restrict__ in,
                                                float* __restrict__ out) {
    int slot = blockIdx.x;
    int t = threadIdx.x;

    int cnt = g_cursor[slot];
    cnt = (cnt > CAP) ? CAP : cnt;
    __syncthreads();                        // everyone has read cnt
    if (t == 0) g_cursor[slot] = 0;         // reset for next graph replay

    const int base = slot * CAP;

    float4 acc = make_float4(0.f, 0.f, 0.f, 0.f);

    int r = 0;
    // 4 rows in flight for memory-level parallelism
    for (; r + 3 < cnt; r += 4) {
        int r0 = g_rows[base + r + 0];
        int r1 = g_rows[base + r + 1];
        int r2 = g_rows[base + r + 2];
        int r3 = g_rows[base + r + 3];
        float4 v0 = __ldg((const float4*)(in + (size_t)r0 * DDIM) + t);
        float4 v1 = __ldg((const float4*)(in + (size_t)r1 * DDIM) + t);
        float4 v2 = __ldg((const float4*)(in + (size_t)r2 * DDIM) + t);
        float4 v3 = __ldg((const float4*)(in + (size_t)r3 * DDIM) + t);
        acc.x += (v0.x + v1.x) + (v2.x + v3.x);
        acc.y += (v0.y + v1.y) + (v2.y + v3.y);
        acc.z += (v0.z + v1.z) + (v2.z + v3.z);
        acc.w += (v0.w + v1.w) + (v2.w + v3.w);
    }
    for (; r < cnt; r++) {
        int row = g_rows[base + r];
        float4 v = __ldg((const float4*)(in + (size_t)row * DDIM) + t);
        acc.x += v.x;
        acc.y += v.y;
        acc.z += v.z;
        acc.w += v.w;
    }

    ((float4*)(out + (size_t)slot * DDIM))[t] = acc;
}

// ---------------------------------------------------------------------------
extern "C" void kernel_launch(void* const* d_in, const int* in_sizes, int n_in,
                              void* d_out, int out_size) {
    const float* data = (const float*)d_in[0];
    const int*   tags = (const int*)d_in[1];
    float*       out  = (float*)d_out;

    k_bucket<<<(NROWS + 511) / 512, 512>>>(tags);
    k_reduce<<<NSLOTS, 256>>>(data, out);
}

// round 6
// speedup vs baseline: 2.0431x; 2.0431x over previous
#include <cuda_runtime.h>
#include <cuda_bf16.h>
#include <stdint.h>

// GatherRouter combine: out[tag[i]] += data[i], 65536 rows x 1024 fp32 -> 16384 slots.
// k_bucket: fixed-capacity bucketing (Poisson(4) per slot; CAP=32 => P(overflow)~1e-19).
// k_reduce: one block/slot. Metadata (count + first 4 indices) fetched in TWO parallel
//           loads, then 4 LDG.128 issued unconditionally (masked lanes -> row 0, L2-hot,
//           weighted 0/1) so every warp has 4 DRAM loads in flight immediately.

#define NROWS   65536          // pow2: mask with 0xFFFF
#define DDIM    1024
#define NSLOTS  16384
#define CAP     32             // one 128B line per bucket

__device__ int g_cursor[NSLOTS];        // zeroed at load; reset by k_reduce each launch
__device__ int g_rows[NSLOTS * CAP];    // 2 MB scratch (stale entries beyond cnt are ok)

// ---------------------------------------------------------------------------
__global__ void k_bucket(const int* __restrict__ tags) {
    int i = blockIdx.x * blockDim.x + threadIdx.x;
    if (i < NROWS) {
        int t = tags[i] & (NSLOTS - 1);
        int p = atomicAdd(&g_cursor[t], 1);
        if (p < CAP) g_rows[t * CAP + p] = i;
    }
}

// ---------------------------------------------------------------------------
__global__ __launch_bounds__(256) void k_reduce(const float* __restrict__ in,
                                                float* __restrict__ out) {
    const int slot = blockIdx.x;
    const int t    = threadIdx.x;

    // Two independent metadata loads, issued in parallel (single L2 round trip).
    int  cnt = g_cursor[slot];
    int4 iv  = __ldg((const int4*)&g_rows[slot * CAP]);
    cnt = (cnt > CAP) ? CAP : cnt;

    // Masked lanes: redirect to row 0 (L2-hot) and weight 0 so loads can issue
    // unconditionally and back-to-back.
    int r0 = (cnt > 0) ? (iv.x & (NROWS - 1)) : 0;
    int r1 = (cnt > 1) ? (iv.y & (NROWS - 1)) : 0;
    int r2 = (cnt > 2) ? (iv.z & (NROWS - 1)) : 0;
    int r3 = (cnt > 3) ? (iv.w & (NROWS - 1)) : 0;
    float w0 = (cnt > 0) ? 1.f : 0.f;
    float w1 = (cnt > 1) ? 1.f : 0.f;
    float w2 = (cnt > 2) ? 1.f : 0.f;
    float w3 = (cnt > 3) ? 1.f : 0.f;

    float4 v0 = __ldg((const float4*)(in + (size_t)r0 * DDIM) + t);
    float4 v1 = __ldg((const float4*)(in + (size_t)r1 * DDIM) + t);
    float4 v2 = __ldg((const float4*)(in + (size_t)r2 * DDIM) + t);
    float4 v3 = __ldg((const float4*)(in + (size_t)r3 * DDIM) + t);

    float4 acc;
    acc.x = fmaf(w0, v0.x, fmaf(w1, v1.x, fmaf(w2, v2.x, w3 * v3.x)));
    acc.y = fmaf(w0, v0.y, fmaf(w1, v1.y, fmaf(w2, v2.y, w3 * v3.y)));
    acc.z = fmaf(w0, v0.z, fmaf(w1, v1.z, fmaf(w2, v2.z, w3 * v3.z)));
    acc.w = fmaf(w0, v0.w, fmaf(w1, v1.w, fmaf(w2, v2.w, w3 * v3.w)));

    // Tail (cnt > 4): ~0.8 extra rows per slot on average; independent pairs.
    int r = 4;
    for (; r + 1 < cnt; r += 2) {
        int ra = g_rows[slot * CAP + r]     & (NROWS - 1);
        int rb = g_rows[slot * CAP + r + 1] & (NROWS - 1);
        float4 va = __ldg((const float4*)(in + (size_t)ra * DDIM) + t);
        float4 vb = __ldg((const float4*)(in + (size_t)rb * DDIM) + t);
        acc.x += va.x + vb.x;
        acc.y += va.y + vb.y;
        acc.z += va.z + vb.z;
        acc.w += va.w + vb.w;
    }
    if (r < cnt) {
        int ra = g_rows[slot * CAP + r] & (NROWS - 1);
        float4 va = __ldg((const float4*)(in + (size_t)ra * DDIM) + t);
        acc.x += va.x;
        acc.y += va.y;
        acc.z += va.z;
        acc.w += va.w;
    }

    ((float4*)(out + (size_t)slot * DDIM))[t] = acc;

    // Reset cursor for the next graph replay (off the critical path).
    __syncthreads();
    if (t == 0) g_cursor[slot] = 0;
}

// ---------------------------------------------------------------------------
extern "C" void kernel_launch(void* const* d_in, const int* in_sizes, int n_in,
                              void* d_out, int out_size) {
    const float* data = (const float*)d_in[0];
    const int*   tags = (const int*)d_in[1];
    float*       out  = (float*)d_out;

    k_bucket<<<NROWS / 128, 128>>>(tags);
    k_reduce<<<NSLOTS, 256>>>(data, out);
}